// round 8
// baseline (speedup 1.0000x reference)
#include <cuda_runtime.h>
#include <cuda_bf16.h>
#include <math.h>

#define NN 100000
#define NE 1600000
#define SCAN_BS 512
#define NBLK ((NN + SCAN_BS - 1) / SCAN_BS)   // 196
#define NCHUNK 4
#define CHK 25088                              // 256-aligned chunk (last = remainder)

// -------- device scratch (allocation-free rule: __device__ globals) --------
__device__ float g_deginv[NN];
__device__ int   g_degi[NN];
__device__ int   g_cursor[NN];
__device__ int   g_rowptr[NN + 1];
__device__ int   g_rowtmp[NN];
__device__ int   g_blocksum[NBLK];
__device__ int   g_blockoff[NBLK];
__device__ int   g_col[NE];                   // CSR: src ids grouped by dst
__device__ float g_bufA0[NN * 64];            // yl (buffer set 0)
__device__ float g_bufB0[NN * 64];            // yr (buffer set 0)
__device__ float g_bufA1[NN * 64];            // yl (buffer set 1)
__device__ float g_bufB1[NN * 64];            // yr (buffer set 1)
__device__ float g_h[NN * 64];                // layer activations

// ---------------------------------------------------------------------------
// CSR build (edge structure fixed across layers -> once per call)
// ---------------------------------------------------------------------------
__global__ void zero_int_kernel() {
    int i = blockIdx.x * blockDim.x + threadIdx.x;
    if (i < NN) { g_degi[i] = 0; g_cursor[i] = 0; }
}

__global__ void deg_count_kernel(const int* __restrict__ dst) {
    int e = blockIdx.x * blockDim.x + threadIdx.x;
    if (e < NE) atomicAdd(&g_degi[dst[e]], 1);
}

__global__ void scan_a_kernel() {
    __shared__ int s[SCAN_BS];
    int t = threadIdx.x;
    int i = blockIdx.x * SCAN_BS + t;
    int v = (i < NN) ? g_degi[i] : 0;
    s[t] = v;
    __syncthreads();
#pragma unroll
    for (int off = 1; off < SCAN_BS; off <<= 1) {
        int x = (t >= off) ? s[t - off] : 0;
        __syncthreads();
        s[t] += x;
        __syncthreads();
    }
    if (i < NN) g_rowtmp[i] = s[t] - v;           // exclusive
    if (t == SCAN_BS - 1) g_blocksum[blockIdx.x] = s[t];
}

__global__ void scan_b_kernel() {
    __shared__ int s[256];
    int t = threadIdx.x;
    int v = (t < NBLK) ? g_blocksum[t] : 0;
    s[t] = v;
    __syncthreads();
#pragma unroll
    for (int off = 1; off < 256; off <<= 1) {
        int x = (t >= off) ? s[t - off] : 0;
        __syncthreads();
        s[t] += x;
        __syncthreads();
    }
    if (t < NBLK) g_blockoff[t] = s[t] - v;       // exclusive
}

__global__ void scan_c_kernel() {
    int i = blockIdx.x * blockDim.x + threadIdx.x;
    if (i < NN) {
        g_rowptr[i] = g_rowtmp[i] + g_blockoff[i / SCAN_BS];
        g_deginv[i] = 1.0f / fmaxf((float)g_degi[i], 1.0f);
    }
    if (i == 0) g_rowptr[NN] = NE;
}

__global__ void csr_fill_kernel(const int* __restrict__ src,
                                const int* __restrict__ dst) {
    int e = blockIdx.x * blockDim.x + threadIdx.x;
    if (e >= NE) return;
    int d = dst[e];
    int pos = g_rowptr[d] + atomicAdd(&g_cursor[d], 1);
    g_col[pos] = src[e];
}

// ---------------------------------------------------------------------------
// Dual projection: yl = h @ Wl ; yr = h @ Wr + b.  DIN fixed at 64.
// SCALAR FFMA; 8 nodes x 4 j per thread, k staged in two phases of 32.
// BUF selects output buffer set (double-buffered across layers for the
// gather/GEMM pipeline WAR hazard). node_base enables chunked launches.
template<int DOUT, bool FROM_GH, int BUF>
__global__ void __launch_bounds__(256, 2)
gemm_dual_kernel(const float* __restrict__ hx,
                 const float* __restrict__ Wl,
                 const float* __restrict__ Wr,
                 const float* __restrict__ bias,
                 int node_base) {
    constexpr int JG  = DOUT / 4;
    constexpr int NG  = 256 / JG;
    constexpr int NPB = NG * 8;
    constexpr int KC  = 32 * NPB / 256;

    __shared__ alignas(16) float sh[32][NPB];
    __shared__ alignas(16) float sWl[32 * DOUT];
    __shared__ alignas(16) float sWr[32 * DOUT];

    const float* __restrict__ h = FROM_GH ? (const float*)g_h : hx;
    float* __restrict__ bufA = BUF ? g_bufA1 : g_bufA0;
    float* __restrict__ bufB = BUF ? g_bufB1 : g_bufB0;

    const int t     = threadIdx.x;
    const int node0 = node_base + blockIdx.x * NPB;
    const int jg    = t % JG;
    const int ng    = t / JG;

    float aL[8][4], aR[8][4];
#pragma unroll
    for (int n = 0; n < 8; n++)
#pragma unroll
        for (int j = 0; j < 4; j++) {
            aL[n][j] = 0.f;
            aR[n][j] = bias[jg * 4 + j];
        }

#pragma unroll
    for (int phase = 0; phase < 2; phase++) {
        const int kbase = phase * 32;
        if (phase) __syncthreads();

        {
            const int r  = t % NPB;
            const int c0 = (t / NPB) * KC;
            const int n  = node0 + r;
            const bool ok = (n < NN);
#pragma unroll
            for (int i = 0; i < KC; i += 4) {
                float4 v = ok ? *(const float4*)&h[(size_t)n * 64 + kbase + c0 + i]
                              : make_float4(0.f, 0.f, 0.f, 0.f);
                sh[c0 + i + 0][r] = v.x;
                sh[c0 + i + 1][r] = v.y;
                sh[c0 + i + 2][r] = v.z;
                sh[c0 + i + 3][r] = v.w;
            }
        }
        for (int i = t; i < 32 * DOUT; i += 256) {
            sWl[i] = Wl[kbase * DOUT + i];
            sWr[i] = Wr[kbase * DOUT + i];
        }
        __syncthreads();

#pragma unroll 8
        for (int k = 0; k < 32; k++) {
            const float4 hv0 = *(const float4*)&sh[k][ng * 8];
            const float4 hv1 = *(const float4*)&sh[k][ng * 8 + 4];
            const float4 wl  = *(const float4*)&sWl[k * DOUT + jg * 4];
            const float4 wr  = *(const float4*)&sWr[k * DOUT + jg * 4];
            const float hn[8]  = {hv0.x, hv0.y, hv0.z, hv0.w,
                                  hv1.x, hv1.y, hv1.z, hv1.w};
            const float wlj[4] = {wl.x, wl.y, wl.z, wl.w};
            const float wrj[4] = {wr.x, wr.y, wr.z, wr.w};
#pragma unroll
            for (int n = 0; n < 8; n++) {
#pragma unroll
                for (int j = 0; j < 4; j++) {
                    aL[n][j] = fmaf(hn[n], wlj[j], aL[n][j]);
                    aR[n][j] = fmaf(hn[n], wrj[j], aR[n][j]);
                }
            }
        }
    }

#pragma unroll
    for (int n = 0; n < 8; n++) {
        const int node = node0 + ng * 8 + n;
        if (node < NN) {
            *(float4*)&bufA[(size_t)node * DOUT + jg * 4] =
                make_float4(aL[n][0], aL[n][1], aL[n][2], aL[n][3]);
            *(float4*)&bufB[(size_t)node * DOUT + jg * 4] =
                make_float4(aR[n][0], aR[n][1], aR[n][2], aR[n][3]);
        }
    }
}

// ---------------------------------------------------------------------------
// Fused gather + epilogue: out[n] = [ELU]( mean_{e in row(n)} yl[col[e]] + yr[n] )
template<int F, bool DO_ELU, bool TO_GH, int BUF>
__global__ void __launch_bounds__(256)
gather_kernel(float* __restrict__ out_param, int node_base, int node_end) {
    constexpr int L = F / 4;               // 16 (F=64) or 8 (F=32)
    const int t    = threadIdx.x;
    const int grp  = t / L;
    const int lane = t % L;
    const int node = node_base + blockIdx.x * (256 / L) + grp;
    if (node >= node_end) return;

    const float* __restrict__ bufA = BUF ? g_bufA1 : g_bufA0;
    const float* __restrict__ bufB = BUF ? g_bufB1 : g_bufB0;

    const int beg = g_rowptr[node];
    const int end = g_rowptr[node + 1];
    const float4* __restrict__ A = (const float4*)bufA;

    float4 a0 = make_float4(0.f, 0.f, 0.f, 0.f);
    float4 a1 = make_float4(0.f, 0.f, 0.f, 0.f);
    int e = beg;
    for (; e + 2 <= end; e += 2) {
        int s0 = g_col[e];
        int s1 = g_col[e + 1];
        float4 v0 = A[(size_t)s0 * L + lane];
        float4 v1 = A[(size_t)s1 * L + lane];
        a0.x += v0.x; a0.y += v0.y; a0.z += v0.z; a0.w += v0.w;
        a1.x += v1.x; a1.y += v1.y; a1.z += v1.z; a1.w += v1.w;
    }
    if (e < end) {
        int s0 = g_col[e];
        float4 v0 = A[(size_t)s0 * L + lane];
        a0.x += v0.x; a0.y += v0.y; a0.z += v0.z; a0.w += v0.w;
    }

    const float di = g_deginv[node];
    const float4 r = ((const float4*)bufB)[(size_t)node * L + lane];
    float4 o;
    o.x = fmaf(a0.x + a1.x, di, r.x);
    o.y = fmaf(a0.y + a1.y, di, r.y);
    o.z = fmaf(a0.z + a1.z, di, r.z);
    o.w = fmaf(a0.w + a1.w, di, r.w);
    if (DO_ELU) {
        o.x = (o.x > 0.f) ? o.x : expm1f(o.x);
        o.y = (o.y > 0.f) ? o.y : expm1f(o.y);
        o.z = (o.z > 0.f) ? o.z : expm1f(o.z);
        o.w = (o.w > 0.f) ? o.w : expm1f(o.w);
    }
    float* out = TO_GH ? (float*)g_h : out_param;
    ((float4*)out)[(size_t)node * L + lane] = o;
}

// ---------------------------------------------------------------------------
extern "C" void kernel_launch(void* const* d_in, const int* in_sizes, int n_in,
                              void* d_out, int out_size) {
    const float* x   = (const float*)d_in[0];
    const int*   ei  = (const int*)d_in[1];
    const float* Wl0 = (const float*)d_in[2];
    const float* Wr0 = (const float*)d_in[3];
    const float* b0  = (const float*)d_in[4];
    const float* Wl1 = (const float*)d_in[5];
    const float* Wr1 = (const float*)d_in[6];
    const float* b1  = (const float*)d_in[7];
    const float* Wl2 = (const float*)d_in[8];
    const float* Wr2 = (const float*)d_in[9];
    const float* b2  = (const float*)d_in[10];
    float* out = (float*)d_out;

    const int* src = ei;
    const int* dst = ei + NE;
    const int TPB = 256;

    // Host-side resources created once (no device allocation).
    static cudaStream_t sB = nullptr;
    static cudaEvent_t  evFork = nullptr, evCSR = nullptr;
    static cudaEvent_t  evG[2][NCHUNK], evM[2];
    if (sB == nullptr) {
        cudaStreamCreateWithFlags(&sB, cudaStreamNonBlocking);
        cudaEventCreateWithFlags(&evFork, cudaEventDisableTiming);
        cudaEventCreateWithFlags(&evCSR, cudaEventDisableTiming);
        for (int p = 0; p < 2; p++) {
            cudaEventCreateWithFlags(&evM[p], cudaEventDisableTiming);
            for (int c = 0; c < NCHUNK; c++)
                cudaEventCreateWithFlags(&evG[p][c], cudaEventDisableTiming);
        }
    }

    // ---- fork: CSR build on side stream, GEMM0 on main stream ----
    cudaEventRecord(evFork, 0);
    cudaStreamWaitEvent(sB, evFork, 0);
    zero_int_kernel<<<(NN + TPB - 1) / TPB, TPB, 0, sB>>>();
    deg_count_kernel<<<(NE + TPB - 1) / TPB, TPB, 0, sB>>>(dst);
    scan_a_kernel<<<NBLK, SCAN_BS, 0, sB>>>();
    scan_b_kernel<<<1, 256, 0, sB>>>();
    scan_c_kernel<<<(NN + TPB - 1) / TPB, TPB, 0, sB>>>();
    csr_fill_kernel<<<(NE + TPB - 1) / TPB, TPB, 0, sB>>>(src, dst);
    cudaEventRecord(evCSR, sB);

    // layer-0 GEMM (full grid) -> buffer set 0
    gemm_dual_kernel<64, false, 0><<<(NN + 127) / 128, 256>>>(x, Wl0, Wr0, b0, 0);
    cudaStreamWaitEvent(0, evCSR, 0);

    // ---- pair 0: gather0 (buf0 -> h) chunks on main, GEMM1 (-> buf1) on sB ----
    for (int c = 0; c < NCHUNK; c++) {
        const int nb = c * CHK;
        const int ne = (c == NCHUNK - 1) ? NN : nb + CHK;
        const int len = ne - nb;
        gather_kernel<64, true, true, 0>
            <<<(len + 15) / 16, 256>>>(nullptr, nb, ne);
        cudaEventRecord(evG[0][c], 0);
        cudaStreamWaitEvent(sB, evG[0][c], 0);
        gemm_dual_kernel<64, true, 1>
            <<<(len + 127) / 128, 256, 0, sB>>>(nullptr, Wl1, Wr1, b1, nb);
    }
    cudaEventRecord(evM[0], sB);
    cudaStreamWaitEvent(0, evM[0], 0);

    // ---- pair 1: gather1 (buf1 -> h) chunks on main, GEMM2 (-> buf0) on sB ----
    for (int c = 0; c < NCHUNK; c++) {
        const int nb = c * CHK;
        const int ne = (c == NCHUNK - 1) ? NN : nb + CHK;
        const int len = ne - nb;
        gather_kernel<64, true, true, 1>
            <<<(len + 15) / 16, 256>>>(nullptr, nb, ne);
        cudaEventRecord(evG[1][c], 0);
        cudaStreamWaitEvent(sB, evG[1][c], 0);
        gemm_dual_kernel<32, true, 0>
            <<<(len + 255) / 256, 256, 0, sB>>>(nullptr, Wl2, Wr2, b2, nb);
    }
    cudaEventRecord(evM[1], sB);
    cudaStreamWaitEvent(0, evM[1], 0);

    // ---- final gather (buf0 -> d_out), full grid ----
    gather_kernel<32, false, false, 0><<<(NN + 31) / 32, 256>>>(out, 0, NN);
}

// round 9
// speedup vs baseline: 1.0640x; 1.0640x over previous
#include <cuda_runtime.h>
#include <cuda_bf16.h>
#include <math.h>

#define NN 100000
#define NE 1600000
#define SCAN_BS 512
#define NBLK ((NN + SCAN_BS - 1) / SCAN_BS)   // 196

// -------- device scratch (allocation-free rule: __device__ globals) --------
__device__ float g_deginv[NN];
__device__ int   g_degi[NN];
__device__ int   g_cursor[NN];
__device__ int   g_rowptr[NN + 1];
__device__ int   g_rowtmp[NN];
__device__ int   g_blocksum[NBLK];
__device__ int   g_blockoff[NBLK];
__device__ int   g_col[NE];                  // CSR: src ids grouped by dst
__device__ float g_bufA[NN * 64];            // yl = h @ Wl
__device__ float g_bufB[NN * 64];            // yr = h @ Wr + b
__device__ float g_h[NN * 64];               // layer activations

// ---------------------------------------------------------------------------
// CSR build (edge structure fixed across layers -> once per call)
// ---------------------------------------------------------------------------
__global__ void zero_int_kernel() {
    int i = blockIdx.x * blockDim.x + threadIdx.x;
    if (i < NN) { g_degi[i] = 0; g_cursor[i] = 0; }
}

__global__ void deg_count_kernel(const int* __restrict__ dst) {
    int e = blockIdx.x * blockDim.x + threadIdx.x;
    if (e < NE) atomicAdd(&g_degi[dst[e]], 1);
}

__global__ void scan_a_kernel() {
    __shared__ int s[SCAN_BS];
    int t = threadIdx.x;
    int i = blockIdx.x * SCAN_BS + t;
    int v = (i < NN) ? g_degi[i] : 0;
    s[t] = v;
    __syncthreads();
#pragma unroll
    for (int off = 1; off < SCAN_BS; off <<= 1) {
        int x = (t >= off) ? s[t - off] : 0;
        __syncthreads();
        s[t] += x;
        __syncthreads();
    }
    if (i < NN) g_rowtmp[i] = s[t] - v;           // exclusive
    if (t == SCAN_BS - 1) g_blocksum[blockIdx.x] = s[t];
}

__global__ void scan_b_kernel() {
    __shared__ int s[256];
    int t = threadIdx.x;
    int v = (t < NBLK) ? g_blocksum[t] : 0;
    s[t] = v;
    __syncthreads();
#pragma unroll
    for (int off = 1; off < 256; off <<= 1) {
        int x = (t >= off) ? s[t - off] : 0;
        __syncthreads();
        s[t] += x;
        __syncthreads();
    }
    if (t < NBLK) g_blockoff[t] = s[t] - v;       // exclusive
}

__global__ void scan_c_kernel() {
    int i = blockIdx.x * blockDim.x + threadIdx.x;
    if (i < NN) {
        g_rowptr[i] = g_rowtmp[i] + g_blockoff[i / SCAN_BS];
        g_deginv[i] = 1.0f / fmaxf((float)g_degi[i], 1.0f);
    }
    if (i == 0) g_rowptr[NN] = NE;
}

__global__ void csr_fill_kernel(const int* __restrict__ src,
                                const int* __restrict__ dst) {
    int e = blockIdx.x * blockDim.x + threadIdx.x;
    if (e >= NE) return;
    int d = dst[e];
    int pos = g_rowptr[d] + atomicAdd(&g_cursor[d], 1);
    g_col[pos] = src[e];
}

// ---------------------------------------------------------------------------
// tf32 helpers
__device__ __forceinline__ unsigned cvt_tf32(float x) {
    unsigned r;
    asm("cvt.rna.tf32.f32 %0, %1;" : "=r"(r) : "f"(x));
    return r;
}
__device__ __forceinline__ void split_tf32(float x, unsigned& hi, unsigned& lo) {
    hi = cvt_tf32(x);
    lo = cvt_tf32(x - __uint_as_float(hi));
}
__device__ __forceinline__ void mma_tf32(float* d,
                                         unsigned a0, unsigned a1,
                                         unsigned a2, unsigned a3,
                                         unsigned b0, unsigned b1) {
    asm("mma.sync.aligned.m16n8k8.row.col.f32.tf32.tf32.f32 "
        "{%0,%1,%2,%3}, {%4,%5,%6,%7}, {%8,%9}, {%0,%1,%2,%3};"
        : "+f"(d[0]), "+f"(d[1]), "+f"(d[2]), "+f"(d[3])
        : "r"(a0), "r"(a1), "r"(a2), "r"(a3), "r"(b0), "r"(b1));
}

// ---------------------------------------------------------------------------
// Dual projection via tensor cores: yl = h @ Wl ; yr = h @ Wr + b.
// m16n8k8 tf32 MMA with 2-term operand split (3xTF32) -> ~fp32 accuracy.
// Block = 256 threads (8 warps); warp owns 16 nodes x DOUT outputs (both mats).
// A fragments LDG'd straight from h (row read by exactly one warp);
// W staged fp32 in shared, split to tf32 hi/lo at use.
template<int DOUT, bool FROM_GH>
__global__ void __launch_bounds__(256, 2)
gemm_dual_kernel(const float* __restrict__ hx,
                 const float* __restrict__ Wl,
                 const float* __restrict__ Wr,
                 const float* __restrict__ bias) {
    constexpr int JT = DOUT / 8;                 // j-tiles (8 or 4)

    __shared__ alignas(16) float sWl[64 * DOUT];
    __shared__ alignas(16) float sWr[64 * DOUT];

    const float* __restrict__ h = FROM_GH ? (const float*)g_h : hx;

    const int t    = threadIdx.x;
    const int wid  = t >> 5;
    const int lane = t & 31;
    const int gid  = lane >> 2;                  // groupID 0..7
    const int tig  = lane & 3;                   // thread-in-group 0..3

    // stage both weight matrices (fp32, coalesced)
    for (int i = t; i < 64 * DOUT; i += 256) {
        sWl[i] = Wl[i];
        sWr[i] = Wr[i];
    }
    __syncthreads();

    const int node0 = blockIdx.x * 128 + wid * 16;
    const int r0 = node0 + gid;                  // rows r0, r0+8
    const bool ok0 = (r0 < NN);
    const bool ok1 = (r0 + 8 < NN);

    // accumulators: d[jt][mat][4]
    float dL[JT][4], dR[JT][4];
#pragma unroll
    for (int jt = 0; jt < JT; jt++) {
        float bc0 = bias[jt * 8 + 2 * tig];
        float bc1 = bias[jt * 8 + 2 * tig + 1];
        dL[jt][0] = dL[jt][1] = dL[jt][2] = dL[jt][3] = 0.f;
        dR[jt][0] = bc0; dR[jt][1] = bc1;
        dR[jt][2] = bc0; dR[jt][3] = bc1;
    }

#pragma unroll
    for (int kb = 0; kb < 8; kb++) {
        const int k0 = kb * 8;
        // A fragment (16x8 slice of h), guarded loads
        float fa0 = ok0 ? h[(size_t)r0 * 64 + k0 + tig] : 0.f;
        float fa1 = ok1 ? h[(size_t)(r0 + 8) * 64 + k0 + tig] : 0.f;
        float fa2 = ok0 ? h[(size_t)r0 * 64 + k0 + tig + 4] : 0.f;
        float fa3 = ok1 ? h[(size_t)(r0 + 8) * 64 + k0 + tig + 4] : 0.f;
        unsigned ah0, al0, ah1, al1, ah2, al2, ah3, al3;
        split_tf32(fa0, ah0, al0);
        split_tf32(fa1, ah1, al1);
        split_tf32(fa2, ah2, al2);
        split_tf32(fa3, ah3, al3);

#pragma unroll
        for (int jt = 0; jt < JT; jt++) {
            const int j0 = jt * 8;
            // B fragments: W[k][n], k rows (tig, tig+4), n col (gid)
            float fbl0 = sWl[(k0 + tig) * DOUT + j0 + gid];
            float fbl1 = sWl[(k0 + tig + 4) * DOUT + j0 + gid];
            float fbr0 = sWr[(k0 + tig) * DOUT + j0 + gid];
            float fbr1 = sWr[(k0 + tig + 4) * DOUT + j0 + gid];
            unsigned bh0, bl0, bh1, bl1;
            split_tf32(fbl0, bh0, bl0);
            split_tf32(fbl1, bh1, bl1);
            // 3xTF32: lo*hi + hi*lo + hi*hi
            mma_tf32(dL[jt], al0, al1, al2, al3, bh0, bh1);
            mma_tf32(dL[jt], ah0, ah1, ah2, ah3, bl0, bl1);
            mma_tf32(dL[jt], ah0, ah1, ah2, ah3, bh0, bh1);

            split_tf32(fbr0, bh0, bl0);
            split_tf32(fbr1, bh1, bl1);
            mma_tf32(dR[jt], al0, al1, al2, al3, bh0, bh1);
            mma_tf32(dR[jt], ah0, ah1, ah2, ah3, bl0, bl1);
            mma_tf32(dR[jt], ah0, ah1, ah2, ah3, bh0, bh1);
        }
    }

    // epilogue: c0/c1 -> row r0 cols (2tig, 2tig+1); c2/c3 -> row r0+8
#pragma unroll
    for (int jt = 0; jt < JT; jt++) {
        const int j0 = jt * 8 + 2 * tig;
        if (ok0) {
            *(float2*)&g_bufA[(size_t)r0 * DOUT + j0] = make_float2(dL[jt][0], dL[jt][1]);
            *(float2*)&g_bufB[(size_t)r0 * DOUT + j0] = make_float2(dR[jt][0], dR[jt][1]);
        }
        if (ok1) {
            *(float2*)&g_bufA[(size_t)(r0 + 8) * DOUT + j0] = make_float2(dL[jt][2], dL[jt][3]);
            *(float2*)&g_bufB[(size_t)(r0 + 8) * DOUT + j0] = make_float2(dR[jt][2], dR[jt][3]);
        }
    }
}

// ---------------------------------------------------------------------------
// Fused gather + epilogue: out[n] = [ELU]( mean_{e in row(n)} yl[col[e]] + yr[n] )
template<int F, bool DO_ELU, bool TO_GH>
__global__ void __launch_bounds__(256)
gather_kernel(float* __restrict__ out_param) {
    constexpr int L = F / 4;               // 16 (F=64) or 8 (F=32)
    const int t    = threadIdx.x;
    const int grp  = t / L;
    const int lane = t % L;
    const int node = blockIdx.x * (256 / L) + grp;
    if (node >= NN) return;

    const int beg = g_rowptr[node];
    const int end = g_rowptr[node + 1];
    const float4* __restrict__ A = (const float4*)g_bufA;

    float4 a0 = make_float4(0.f, 0.f, 0.f, 0.f);
    float4 a1 = make_float4(0.f, 0.f, 0.f, 0.f);
    int e = beg;
    for (; e + 2 <= end; e += 2) {
        int s0 = g_col[e];
        int s1 = g_col[e + 1];
        float4 v0 = A[(size_t)s0 * L + lane];
        float4 v1 = A[(size_t)s1 * L + lane];
        a0.x += v0.x; a0.y += v0.y; a0.z += v0.z; a0.w += v0.w;
        a1.x += v1.x; a1.y += v1.y; a1.z += v1.z; a1.w += v1.w;
    }
    if (e < end) {
        int s0 = g_col[e];
        float4 v0 = A[(size_t)s0 * L + lane];
        a0.x += v0.x; a0.y += v0.y; a0.z += v0.z; a0.w += v0.w;
    }

    const float di = g_deginv[node];
    const float4 r = ((const float4*)g_bufB)[(size_t)node * L + lane];
    float4 o;
    o.x = fmaf(a0.x + a1.x, di, r.x);
    o.y = fmaf(a0.y + a1.y, di, r.y);
    o.z = fmaf(a0.z + a1.z, di, r.z);
    o.w = fmaf(a0.w + a1.w, di, r.w);
    if (DO_ELU) {
        o.x = (o.x > 0.f) ? o.x : expm1f(o.x);
        o.y = (o.y > 0.f) ? o.y : expm1f(o.y);
        o.z = (o.z > 0.f) ? o.z : expm1f(o.z);
        o.w = (o.w > 0.f) ? o.w : expm1f(o.w);
    }
    float* out = TO_GH ? (float*)g_h : out_param;
    ((float4*)out)[(size_t)node * L + lane] = o;
}

// ---------------------------------------------------------------------------
extern "C" void kernel_launch(void* const* d_in, const int* in_sizes, int n_in,
                              void* d_out, int out_size) {
    const float* x   = (const float*)d_in[0];
    const int*   ei  = (const int*)d_in[1];
    const float* Wl0 = (const float*)d_in[2];
    const float* Wr0 = (const float*)d_in[3];
    const float* b0  = (const float*)d_in[4];
    const float* Wl1 = (const float*)d_in[5];
    const float* Wr1 = (const float*)d_in[6];
    const float* b1  = (const float*)d_in[7];
    const float* Wl2 = (const float*)d_in[8];
    const float* Wr2 = (const float*)d_in[9];
    const float* b2  = (const float*)d_in[10];
    float* out = (float*)d_out;

    const int* src = ei;
    const int* dst = ei + NE;

    const int TPB = 256;
    const int gemm_blocks = (NN + 127) / 128;     // 782
    const int gather_blocks64 = (NN + 15) / 16;
    const int gather_blocks32 = (NN + 31) / 32;

    // Side stream + events for overlapping the CSR build with layer-0 GEMM.
    static cudaStream_t s_side = nullptr;
    static cudaEvent_t  s_fork = nullptr, s_join = nullptr;
    if (s_side == nullptr) {
        cudaStreamCreateWithFlags(&s_side, cudaStreamNonBlocking);
        cudaEventCreateWithFlags(&s_fork, cudaEventDisableTiming);
        cudaEventCreateWithFlags(&s_join, cudaEventDisableTiming);
    }

    // ---- fork: CSR build on side stream, GEMM0 on main stream ----
    cudaEventRecord(s_fork, 0);
    cudaStreamWaitEvent(s_side, s_fork, 0);

    zero_int_kernel<<<(NN + TPB - 1) / TPB, TPB, 0, s_side>>>();
    deg_count_kernel<<<(NE + TPB - 1) / TPB, TPB, 0, s_side>>>(dst);
    scan_a_kernel<<<NBLK, SCAN_BS, 0, s_side>>>();
    scan_b_kernel<<<1, 256, 0, s_side>>>();
    scan_c_kernel<<<(NN + TPB - 1) / TPB, TPB, 0, s_side>>>();
    csr_fill_kernel<<<(NE + TPB - 1) / TPB, TPB, 0, s_side>>>(src, dst);
    cudaEventRecord(s_join, s_side);

    gemm_dual_kernel<64, false><<<gemm_blocks, 256>>>(x, Wl0, Wr0, b0);

    // ---- join: gather0 needs both CSR and bufA/bufB ----
    cudaStreamWaitEvent(0, s_join, 0);
    gather_kernel<64, true, true><<<gather_blocks64, 256>>>(nullptr);

    // ---- layer 1: 64 -> 64, ELU ----
    gemm_dual_kernel<64, true><<<gemm_blocks, 256>>>(nullptr, Wl1, Wr1, b1);
    gather_kernel<64, true, true><<<gather_blocks64, 256>>>(nullptr);

    // ---- layer 2: 64 -> 32, no activation, straight to d_out ----
    gemm_dual_kernel<32, true><<<gemm_blocks, 256>>>(nullptr, Wl2, Wr2, b2);
    gather_kernel<32, false, false><<<gather_blocks32, 256>>>(out);
}

// round 10
// speedup vs baseline: 1.1339x; 1.0658x over previous
#include <cuda_runtime.h>
#include <cuda_bf16.h>
#include <math.h>

#define NN 100000
#define NE 1600000
#define SCAN_BS 512
#define NBLK ((NN + SCAN_BS - 1) / SCAN_BS)   // 196

// -------- device scratch (allocation-free rule: __device__ globals) --------
__device__ float g_deginv[NN];
__device__ int   g_degi[NN];
__device__ int   g_cursor[NN];
__device__ int   g_rowptr[NN + 1];
__device__ int   g_rowtmp[NN];
__device__ int   g_blocksum[NBLK];
__device__ int   g_blockoff[NBLK];
__device__ int   g_col[NE];                  // CSR: src ids grouped by dst
__device__ float g_bufA[NN * 64];            // yl = h @ Wl
__device__ float g_bufB[NN * 64];            // yr = h @ Wr + b
__device__ float g_h[NN * 64];               // layer activations

// ---------------------------------------------------------------------------
// CSR build (edge structure fixed across layers -> once per call)
// ---------------------------------------------------------------------------
__global__ void zero_int_kernel() {
    int i = blockIdx.x * blockDim.x + threadIdx.x;
    if (i < NN) { g_degi[i] = 0; g_cursor[i] = 0; }
}

__global__ void deg_count_kernel(const int* __restrict__ dst) {
    int e = blockIdx.x * blockDim.x + threadIdx.x;
    if (e < NE) atomicAdd(&g_degi[dst[e]], 1);
}

__global__ void scan_a_kernel() {
    __shared__ int s[SCAN_BS];
    int t = threadIdx.x;
    int i = blockIdx.x * SCAN_BS + t;
    int v = (i < NN) ? g_degi[i] : 0;
    s[t] = v;
    __syncthreads();
#pragma unroll
    for (int off = 1; off < SCAN_BS; off <<= 1) {
        int x = (t >= off) ? s[t - off] : 0;
        __syncthreads();
        s[t] += x;
        __syncthreads();
    }
    if (i < NN) g_rowtmp[i] = s[t] - v;           // exclusive
    if (t == SCAN_BS - 1) g_blocksum[blockIdx.x] = s[t];
}

__global__ void scan_b_kernel() {
    __shared__ int s[256];
    int t = threadIdx.x;
    int v = (t < NBLK) ? g_blocksum[t] : 0;
    s[t] = v;
    __syncthreads();
#pragma unroll
    for (int off = 1; off < 256; off <<= 1) {
        int x = (t >= off) ? s[t - off] : 0;
        __syncthreads();
        s[t] += x;
        __syncthreads();
    }
    if (t < NBLK) g_blockoff[t] = s[t] - v;       // exclusive
}

__global__ void scan_c_kernel() {
    int i = blockIdx.x * blockDim.x + threadIdx.x;
    if (i < NN) {
        g_rowptr[i] = g_rowtmp[i] + g_blockoff[i / SCAN_BS];
        g_deginv[i] = 1.0f / fmaxf((float)g_degi[i], 1.0f);
    }
    if (i == 0) g_rowptr[NN] = NE;
}

__global__ void csr_fill_kernel(const int* __restrict__ src,
                                const int* __restrict__ dst) {
    int e = blockIdx.x * blockDim.x + threadIdx.x;
    if (e >= NE) return;
    int d = dst[e];
    int pos = g_rowptr[d] + atomicAdd(&g_cursor[d], 1);
    g_col[pos] = src[e];
}

// ---------------------------------------------------------------------------
// tf32 helpers
__device__ __forceinline__ unsigned cvt_tf32(float x) {
    unsigned r;
    asm("cvt.rna.tf32.f32 %0, %1;" : "=r"(r) : "f"(x));
    return r;
}
__device__ __forceinline__ void split_tf32(float x, unsigned& hi, unsigned& lo) {
    hi = cvt_tf32(x);
    lo = cvt_tf32(x - __uint_as_float(hi));
}
__device__ __forceinline__ void mma_tf32(float* d,
                                         unsigned a0, unsigned a1,
                                         unsigned a2, unsigned a3,
                                         unsigned b0, unsigned b1) {
    asm("mma.sync.aligned.m16n8k8.row.col.f32.tf32.tf32.f32 "
        "{%0,%1,%2,%3}, {%4,%5,%6,%7}, {%8,%9}, {%0,%1,%2,%3};"
        : "+f"(d[0]), "+f"(d[1]), "+f"(d[2]), "+f"(d[3])
        : "r"(a0), "r"(a1), "r"(a2), "r"(a3), "r"(b0), "r"(b1));
}

// ---------------------------------------------------------------------------
// Dual projection via tensor cores (3xTF32, ~fp32 accuracy).
// W is split hi/lo ONCE at stage time into per-fragment PACKED smem layout:
//   sB[frag][lane*2 + i] = W[kb*8 + tig + 4*i][jt*8 + gid]   (frag = kb*JT+jt)
// so the inner loop is pure LDS.64 (conflict-free) + MMA — no cvt, no
// bank conflicts (the two defects of the round-9 version).
// Dynamic smem: 4 packed arrays (Wl/Wr x hi/lo) of 64*DOUT floats.
template<int DOUT, bool FROM_GH>
__global__ void __launch_bounds__(256)
gemm_dual_kernel(const float* __restrict__ hx,
                 const float* __restrict__ Wl,
                 const float* __restrict__ Wr,
                 const float* __restrict__ bias) {
    constexpr int JT    = DOUT / 8;              // j-tiles (8 or 4)
    constexpr int FRAGS = 8 * JT;                // (kb, jt) fragments
    constexpr int FSZ   = FRAGS * 64;            // floats per packed array

    extern __shared__ float smem[];
    float* sBlh = smem;
    float* sBll = sBlh + FSZ;
    float* sBrh = sBll + FSZ;
    float* sBrl = sBrh + FSZ;

    const float* __restrict__ h = FROM_GH ? (const float*)g_h : hx;

    const int t    = threadIdx.x;
    const int wid  = t >> 5;
    const int lane = t & 31;
    const int gid  = lane >> 2;                  // groupID 0..7
    const int tig  = lane & 3;                   // thread-in-group 0..3

    // ---- stage: split W into packed tf32 hi/lo fragments ----
    for (int idx = t; idx < FSZ; idx += 256) {
        const int frag = idx >> 6;
        const int li   = idx & 63;
        const int ln   = li >> 1;
        const int i    = li & 1;
        const int kb   = frag / JT;
        const int jt   = frag % JT;
        const int k    = kb * 8 + (ln & 3) + 4 * i;
        const int j    = jt * 8 + (ln >> 2);
        unsigned hi, lo;
        split_tf32(Wl[k * DOUT + j], hi, lo);
        sBlh[idx] = __uint_as_float(hi);
        sBll[idx] = __uint_as_float(lo);
        split_tf32(Wr[k * DOUT + j], hi, lo);
        sBrh[idx] = __uint_as_float(hi);
        sBrl[idx] = __uint_as_float(lo);
    }
    __syncthreads();

    const int node0 = blockIdx.x * 128 + wid * 16;
    const int r0 = node0 + gid;                  // rows r0, r0+8
    const bool ok0 = (r0 < NN);
    const bool ok1 = (r0 + 8 < NN);

    float dL[JT][4], dR[JT][4];
#pragma unroll
    for (int jt = 0; jt < JT; jt++) {
        float bc0 = bias[jt * 8 + 2 * tig];
        float bc1 = bias[jt * 8 + 2 * tig + 1];
        dL[jt][0] = dL[jt][1] = dL[jt][2] = dL[jt][3] = 0.f;
        dR[jt][0] = bc0; dR[jt][1] = bc1;
        dR[jt][2] = bc0; dR[jt][3] = bc1;
    }

#pragma unroll
    for (int kb = 0; kb < 8; kb++) {
        const int k0 = kb * 8;
        float fa0 = ok0 ? h[(size_t)r0 * 64 + k0 + tig] : 0.f;
        float fa1 = ok1 ? h[(size_t)(r0 + 8) * 64 + k0 + tig] : 0.f;
        float fa2 = ok0 ? h[(size_t)r0 * 64 + k0 + tig + 4] : 0.f;
        float fa3 = ok1 ? h[(size_t)(r0 + 8) * 64 + k0 + tig + 4] : 0.f;
        unsigned ah0, al0, ah1, al1, ah2, al2, ah3, al3;
        split_tf32(fa0, ah0, al0);
        split_tf32(fa1, ah1, al1);
        split_tf32(fa2, ah2, al2);
        split_tf32(fa3, ah3, al3);

#pragma unroll
        for (int jt = 0; jt < JT; jt++) {
            const int fbase = (kb * JT + jt) * 64 + lane * 2;
            const float2 blh = *(const float2*)&sBlh[fbase];
            const float2 bll = *(const float2*)&sBll[fbase];
            const float2 brh = *(const float2*)&sBrh[fbase];
            const float2 brl = *(const float2*)&sBrl[fbase];

            mma_tf32(dL[jt], al0, al1, al2, al3,
                     __float_as_uint(blh.x), __float_as_uint(blh.y));
            mma_tf32(dL[jt], ah0, ah1, ah2, ah3,
                     __float_as_uint(bll.x), __float_as_uint(bll.y));
            mma_tf32(dL[jt], ah0, ah1, ah2, ah3,
                     __float_as_uint(blh.x), __float_as_uint(blh.y));

            mma_tf32(dR[jt], al0, al1, al2, al3,
                     __float_as_uint(brh.x), __float_as_uint(brh.y));
            mma_tf32(dR[jt], ah0, ah1, ah2, ah3,
                     __float_as_uint(brl.x), __float_as_uint(brl.y));
            mma_tf32(dR[jt], ah0, ah1, ah2, ah3,
                     __float_as_uint(brh.x), __float_as_uint(brh.y));
        }
    }

    // epilogue: c0/c1 -> row r0 cols (2tig, 2tig+1); c2/c3 -> row r0+8
#pragma unroll
    for (int jt = 0; jt < JT; jt++) {
        const int j0 = jt * 8 + 2 * tig;
        if (ok0) {
            *(float2*)&g_bufA[(size_t)r0 * DOUT + j0] = make_float2(dL[jt][0], dL[jt][1]);
            *(float2*)&g_bufB[(size_t)r0 * DOUT + j0] = make_float2(dR[jt][0], dR[jt][1]);
        }
        if (ok1) {
            *(float2*)&g_bufA[(size_t)(r0 + 8) * DOUT + j0] = make_float2(dL[jt][2], dL[jt][3]);
            *(float2*)&g_bufB[(size_t)(r0 + 8) * DOUT + j0] = make_float2(dR[jt][2], dR[jt][3]);
        }
    }
}

// ---------------------------------------------------------------------------
// Fused gather + epilogue: out[n] = [ELU]( mean_{e in row(n)} yl[col[e]] + yr[n] )
template<int F, bool DO_ELU, bool TO_GH>
__global__ void __launch_bounds__(256)
gather_kernel(float* __restrict__ out_param) {
    constexpr int L = F / 4;               // 16 (F=64) or 8 (F=32)
    const int t    = threadIdx.x;
    const int grp  = t / L;
    const int lane = t % L;
    const int node = blockIdx.x * (256 / L) + grp;
    if (node >= NN) return;

    const int beg = g_rowptr[node];
    const int end = g_rowptr[node + 1];
    const float4* __restrict__ A = (const float4*)g_bufA;

    float4 a0 = make_float4(0.f, 0.f, 0.f, 0.f);
    float4 a1 = make_float4(0.f, 0.f, 0.f, 0.f);
    int e = beg;
    for (; e + 2 <= end; e += 2) {
        int s0 = g_col[e];
        int s1 = g_col[e + 1];
        float4 v0 = A[(size_t)s0 * L + lane];
        float4 v1 = A[(size_t)s1 * L + lane];
        a0.x += v0.x; a0.y += v0.y; a0.z += v0.z; a0.w += v0.w;
        a1.x += v1.x; a1.y += v1.y; a1.z += v1.z; a1.w += v1.w;
    }
    if (e < end) {
        int s0 = g_col[e];
        float4 v0 = A[(size_t)s0 * L + lane];
        a0.x += v0.x; a0.y += v0.y; a0.z += v0.z; a0.w += v0.w;
    }

    const float di = g_deginv[node];
    const float4 r = ((const float4*)g_bufB)[(size_t)node * L + lane];
    float4 o;
    o.x = fmaf(a0.x + a1.x, di, r.x);
    o.y = fmaf(a0.y + a1.y, di, r.y);
    o.z = fmaf(a0.z + a1.z, di, r.z);
    o.w = fmaf(a0.w + a1.w, di, r.w);
    if (DO_ELU) {
        o.x = (o.x > 0.f) ? o.x : expm1f(o.x);
        o.y = (o.y > 0.f) ? o.y : expm1f(o.y);
        o.z = (o.z > 0.f) ? o.z : expm1f(o.z);
        o.w = (o.w > 0.f) ? o.w : expm1f(o.w);
    }
    float* out = TO_GH ? (float*)g_h : out_param;
    ((float4*)out)[(size_t)node * L + lane] = o;
}

// ---------------------------------------------------------------------------
extern "C" void kernel_launch(void* const* d_in, const int* in_sizes, int n_in,
                              void* d_out, int out_size) {
    const float* x   = (const float*)d_in[0];
    const int*   ei  = (const int*)d_in[1];
    const float* Wl0 = (const float*)d_in[2];
    const float* Wr0 = (const float*)d_in[3];
    const float* b0  = (const float*)d_in[4];
    const float* Wl1 = (const float*)d_in[5];
    const float* Wr1 = (const float*)d_in[6];
    const float* b1  = (const float*)d_in[7];
    const float* Wl2 = (const float*)d_in[8];
    const float* Wr2 = (const float*)d_in[9];
    const float* b2  = (const float*)d_in[10];
    float* out = (float*)d_out;

    const int* src = ei;
    const int* dst = ei + NE;

    const int TPB = 256;
    const int gemm_blocks = (NN + 127) / 128;     // 782
    const int gather_blocks64 = (NN + 15) / 16;
    const int gather_blocks32 = (NN + 31) / 32;

    const int SM64 = 4 * 64 * 64 * 4;   // 65536 B dynamic smem (DOUT=64)
    const int SM32 = 4 * 64 * 32 * 4;   // 32768 B (DOUT=32)

    // One-time host-side setup (streams/events + smem limits).
    static cudaStream_t s_side = nullptr;
    static cudaEvent_t  s_fork = nullptr, s_join = nullptr;
    if (s_side == nullptr) {
        cudaStreamCreateWithFlags(&s_side, cudaStreamNonBlocking);
        cudaEventCreateWithFlags(&s_fork, cudaEventDisableTiming);
        cudaEventCreateWithFlags(&s_join, cudaEventDisableTiming);
        cudaFuncSetAttribute(gemm_dual_kernel<64, false>,
                             cudaFuncAttributeMaxDynamicSharedMemorySize, SM64);
        cudaFuncSetAttribute(gemm_dual_kernel<64, true>,
                             cudaFuncAttributeMaxDynamicSharedMemorySize, SM64);
        cudaFuncSetAttribute(gemm_dual_kernel<32, true>,
                             cudaFuncAttributeMaxDynamicSharedMemorySize, SM32);
    }

    // ---- fork: CSR build on side stream, GEMM0 on main stream ----
    cudaEventRecord(s_fork, 0);
    cudaStreamWaitEvent(s_side, s_fork, 0);

    zero_int_kernel<<<(NN + TPB - 1) / TPB, TPB, 0, s_side>>>();
    deg_count_kernel<<<(NE + TPB - 1) / TPB, TPB, 0, s_side>>>(dst);
    scan_a_kernel<<<NBLK, SCAN_BS, 0, s_side>>>();
    scan_b_kernel<<<1, 256, 0, s_side>>>();
    scan_c_kernel<<<(NN + TPB - 1) / TPB, TPB, 0, s_side>>>();
    csr_fill_kernel<<<(NE + TPB - 1) / TPB, TPB, 0, s_side>>>(src, dst);
    cudaEventRecord(s_join, s_side);

    gemm_dual_kernel<64, false><<<gemm_blocks, 256, SM64>>>(x, Wl0, Wr0, b0);

    // ---- join: gather0 needs both CSR and bufA/bufB ----
    cudaStreamWaitEvent(0, s_join, 0);
    gather_kernel<64, true, true><<<gather_blocks64, 256>>>(nullptr);

    // ---- layer 1: 64 -> 64, ELU ----
    gemm_dual_kernel<64, true><<<gemm_blocks, 256, SM64>>>(nullptr, Wl1, Wr1, b1);
    gather_kernel<64, true, true><<<gather_blocks64, 256>>>(nullptr);

    // ---- layer 2: 64 -> 32, no activation, straight to d_out ----
    gemm_dual_kernel<32, true><<<gemm_blocks, 256, SM32>>>(nullptr, Wl2, Wr2, b2);
    gather_kernel<32, false, false><<<gather_blocks32, 256>>>(out);
}

// round 11
// speedup vs baseline: 1.2374x; 1.0913x over previous
#include <cuda_runtime.h>
#include <cuda_fp16.h>
#include <math.h>

#define NN 100000
#define NE 1600000
#define SCAN_BS 512
#define NBLK ((NN + SCAN_BS - 1) / SCAN_BS)   // 196

// -------- device scratch (allocation-free rule: __device__ globals) --------
__device__ float  g_deginv[NN];
__device__ int    g_degi[NN];
__device__ int    g_cursor[NN];
__device__ int    g_rowptr[NN + 1];
__device__ int    g_rowtmp[NN];
__device__ int    g_blocksum[NBLK];
__device__ int    g_blockoff[NBLK];
__device__ int    g_col[NE];                  // CSR: src ids grouped by dst
__device__ __half g_bufAh[NN * 64];           // yl = h @ Wl   (fp16: gather reads this)
__device__ float  g_bufB[NN * 64];            // yr = h @ Wr + b (fp32)
__device__ float  g_h[NN * 64];               // layer activations

// ---------------------------------------------------------------------------
// CSR build (edge structure fixed across layers -> once per call)
// ---------------------------------------------------------------------------
__global__ void zero_int_kernel() {
    int i = blockIdx.x * blockDim.x + threadIdx.x;
    if (i < NN) { g_degi[i] = 0; g_cursor[i] = 0; }
}

__global__ void deg_count_kernel(const int* __restrict__ dst) {
    int e = blockIdx.x * blockDim.x + threadIdx.x;
    if (e < NE) atomicAdd(&g_degi[dst[e]], 1);
}

__global__ void scan_a_kernel() {
    __shared__ int s[SCAN_BS];
    int t = threadIdx.x;
    int i = blockIdx.x * SCAN_BS + t;
    int v = (i < NN) ? g_degi[i] : 0;
    s[t] = v;
    __syncthreads();
#pragma unroll
    for (int off = 1; off < SCAN_BS; off <<= 1) {
        int x = (t >= off) ? s[t - off] : 0;
        __syncthreads();
        s[t] += x;
        __syncthreads();
    }
    if (i < NN) g_rowtmp[i] = s[t] - v;           // exclusive
    if (t == SCAN_BS - 1) g_blocksum[blockIdx.x] = s[t];
}

__global__ void scan_b_kernel() {
    __shared__ int s[256];
    int t = threadIdx.x;
    int v = (t < NBLK) ? g_blocksum[t] : 0;
    s[t] = v;
    __syncthreads();
#pragma unroll
    for (int off = 1; off < 256; off <<= 1) {
        int x = (t >= off) ? s[t - off] : 0;
        __syncthreads();
        s[t] += x;
        __syncthreads();
    }
    if (t < NBLK) g_blockoff[t] = s[t] - v;       // exclusive
}

__global__ void scan_c_kernel() {
    int i = blockIdx.x * blockDim.x + threadIdx.x;
    if (i < NN) {
        g_rowptr[i] = g_rowtmp[i] + g_blockoff[i / SCAN_BS];
        g_deginv[i] = 1.0f / fmaxf((float)g_degi[i], 1.0f);
    }
    if (i == 0) g_rowptr[NN] = NE;
}

__global__ void csr_fill_kernel(const int* __restrict__ src,
                                const int* __restrict__ dst) {
    int e = blockIdx.x * blockDim.x + threadIdx.x;
    if (e >= NE) return;
    int d = dst[e];
    int pos = g_rowptr[d] + atomicAdd(&g_cursor[d], 1);
    g_col[pos] = src[e];
}

// ---------------------------------------------------------------------------
// tf32 helpers
__device__ __forceinline__ unsigned cvt_tf32(float x) {
    unsigned r;
    asm("cvt.rna.tf32.f32 %0, %1;" : "=r"(r) : "f"(x));
    return r;
}
__device__ __forceinline__ void split_tf32(float x, unsigned& hi, unsigned& lo) {
    hi = cvt_tf32(x);
    lo = cvt_tf32(x - __uint_as_float(hi));
}
__device__ __forceinline__ void mma_tf32(float* d,
                                         unsigned a0, unsigned a1,
                                         unsigned a2, unsigned a3,
                                         unsigned b0, unsigned b1) {
    asm("mma.sync.aligned.m16n8k8.row.col.f32.tf32.tf32.f32 "
        "{%0,%1,%2,%3}, {%4,%5,%6,%7}, {%8,%9}, {%0,%1,%2,%3};"
        : "+f"(d[0]), "+f"(d[1]), "+f"(d[2]), "+f"(d[3])
        : "r"(a0), "r"(a1), "r"(a2), "r"(a3), "r"(b0), "r"(b1));
}

// ---------------------------------------------------------------------------
// Dual projection via tensor cores (3xTF32, ~fp32 accuracy).
// yl written as fp16 (g_bufAh) for the bandwidth-bound gather; yr fp32.
template<int DOUT, bool FROM_GH>
__global__ void __launch_bounds__(256)
gemm_dual_kernel(const float* __restrict__ hx,
                 const float* __restrict__ Wl,
                 const float* __restrict__ Wr,
                 const float* __restrict__ bias) {
    constexpr int JT    = DOUT / 8;              // j-tiles (8 or 4)
    constexpr int FRAGS = 8 * JT;                // (kb, jt) fragments
    constexpr int FSZ   = FRAGS * 64;            // floats per packed array

    extern __shared__ float smem[];
    float* sBlh = smem;
    float* sBll = sBlh + FSZ;
    float* sBrh = sBll + FSZ;
    float* sBrl = sBrh + FSZ;

    const float* __restrict__ h = FROM_GH ? (const float*)g_h : hx;

    const int t    = threadIdx.x;
    const int wid  = t >> 5;
    const int lane = t & 31;
    const int gid  = lane >> 2;                  // groupID 0..7
    const int tig  = lane & 3;                   // thread-in-group 0..3

    // ---- stage: split W into packed tf32 hi/lo fragments ----
    for (int idx = t; idx < FSZ; idx += 256) {
        const int frag = idx >> 6;
        const int li   = idx & 63;
        const int ln   = li >> 1;
        const int i    = li & 1;
        const int kb   = frag / JT;
        const int jt   = frag % JT;
        const int k    = kb * 8 + (ln & 3) + 4 * i;
        const int j    = jt * 8 + (ln >> 2);
        unsigned hi, lo;
        split_tf32(Wl[k * DOUT + j], hi, lo);
        sBlh[idx] = __uint_as_float(hi);
        sBll[idx] = __uint_as_float(lo);
        split_tf32(Wr[k * DOUT + j], hi, lo);
        sBrh[idx] = __uint_as_float(hi);
        sBrl[idx] = __uint_as_float(lo);
    }
    __syncthreads();

    const int node0 = blockIdx.x * 128 + wid * 16;
    const int r0 = node0 + gid;                  // rows r0, r0+8
    const bool ok0 = (r0 < NN);
    const bool ok1 = (r0 + 8 < NN);

    float dL[JT][4], dR[JT][4];
#pragma unroll
    for (int jt = 0; jt < JT; jt++) {
        float bc0 = bias[jt * 8 + 2 * tig];
        float bc1 = bias[jt * 8 + 2 * tig + 1];
        dL[jt][0] = dL[jt][1] = dL[jt][2] = dL[jt][3] = 0.f;
        dR[jt][0] = bc0; dR[jt][1] = bc1;
        dR[jt][2] = bc0; dR[jt][3] = bc1;
    }

#pragma unroll
    for (int kb = 0; kb < 8; kb++) {
        const int k0 = kb * 8;
        float fa0 = ok0 ? h[(size_t)r0 * 64 + k0 + tig] : 0.f;
        float fa1 = ok1 ? h[(size_t)(r0 + 8) * 64 + k0 + tig] : 0.f;
        float fa2 = ok0 ? h[(size_t)r0 * 64 + k0 + tig + 4] : 0.f;
        float fa3 = ok1 ? h[(size_t)(r0 + 8) * 64 + k0 + tig + 4] : 0.f;
        unsigned ah0, al0, ah1, al1, ah2, al2, ah3, al3;
        split_tf32(fa0, ah0, al0);
        split_tf32(fa1, ah1, al1);
        split_tf32(fa2, ah2, al2);
        split_tf32(fa3, ah3, al3);

#pragma unroll
        for (int jt = 0; jt < JT; jt++) {
            const int fbase = (kb * JT + jt) * 64 + lane * 2;
            const float2 blh = *(const float2*)&sBlh[fbase];
            const float2 bll = *(const float2*)&sBll[fbase];
            const float2 brh = *(const float2*)&sBrh[fbase];
            const float2 brl = *(const float2*)&sBrl[fbase];

            mma_tf32(dL[jt], al0, al1, al2, al3,
                     __float_as_uint(blh.x), __float_as_uint(blh.y));
            mma_tf32(dL[jt], ah0, ah1, ah2, ah3,
                     __float_as_uint(bll.x), __float_as_uint(bll.y));
            mma_tf32(dL[jt], ah0, ah1, ah2, ah3,
                     __float_as_uint(blh.x), __float_as_uint(blh.y));

            mma_tf32(dR[jt], al0, al1, al2, al3,
                     __float_as_uint(brh.x), __float_as_uint(brh.y));
            mma_tf32(dR[jt], ah0, ah1, ah2, ah3,
                     __float_as_uint(brl.x), __float_as_uint(brl.y));
            mma_tf32(dR[jt], ah0, ah1, ah2, ah3,
                     __float_as_uint(brh.x), __float_as_uint(brh.y));
        }
    }

    // epilogue: yl -> fp16 (half2 stores), yr -> fp32
#pragma unroll
    for (int jt = 0; jt < JT; jt++) {
        const int j0 = jt * 8 + 2 * tig;
        if (ok0) {
            *(__half2*)&g_bufAh[(size_t)r0 * DOUT + j0] =
                __floats2half2_rn(dL[jt][0], dL[jt][1]);
            *(float2*)&g_bufB[(size_t)r0 * DOUT + j0] = make_float2(dR[jt][0], dR[jt][1]);
        }
        if (ok1) {
            *(__half2*)&g_bufAh[(size_t)(r0 + 8) * DOUT + j0] =
                __floats2half2_rn(dL[jt][2], dL[jt][3]);
            *(float2*)&g_bufB[(size_t)(r0 + 8) * DOUT + j0] = make_float2(dR[jt][2], dR[jt][3]);
        }
    }
}

// ---------------------------------------------------------------------------
// Fused gather + epilogue: out[n] = [ELU]( mean_e yl_h16[col[e]] + yr[n] )
// yl is fp16: one uint4 (8 halves = 16B) per lane per edge -> 128B/edge (F=64).
// Accumulation in fp32.
template<int F, bool DO_ELU, bool TO_GH>
__global__ void __launch_bounds__(256)
gather_kernel(float* __restrict__ out_param) {
    constexpr int L = F / 8;               // lanes/node: 8 (F=64) or 4 (F=32)
    const int t    = threadIdx.x;
    const int grp  = t / L;
    const int lane = t % L;
    const int node = blockIdx.x * (256 / L) + grp;
    if (node >= NN) return;

    const int beg = g_rowptr[node];
    const int end = g_rowptr[node + 1];
    const __half* __restrict__ A = g_bufAh;

    float a[8] = {0.f, 0.f, 0.f, 0.f, 0.f, 0.f, 0.f, 0.f};
    for (int e = beg; e < end; e++) {
        const int s = g_col[e];
        const uint4 v = *(const uint4*)&A[(size_t)s * F + lane * 8];
        const __half2* hp = (const __half2*)&v;
        float2 f0 = __half22float2(hp[0]);
        float2 f1 = __half22float2(hp[1]);
        float2 f2 = __half22float2(hp[2]);
        float2 f3 = __half22float2(hp[3]);
        a[0] += f0.x; a[1] += f0.y;
        a[2] += f1.x; a[3] += f1.y;
        a[4] += f2.x; a[5] += f2.y;
        a[6] += f3.x; a[7] += f3.y;
    }

    const float di = g_deginv[node];
    const float4 r0 = *(const float4*)&g_bufB[(size_t)node * F + lane * 8];
    const float4 r1 = *(const float4*)&g_bufB[(size_t)node * F + lane * 8 + 4];
    float o[8];
    o[0] = fmaf(a[0], di, r0.x);
    o[1] = fmaf(a[1], di, r0.y);
    o[2] = fmaf(a[2], di, r0.z);
    o[3] = fmaf(a[3], di, r0.w);
    o[4] = fmaf(a[4], di, r1.x);
    o[5] = fmaf(a[5], di, r1.y);
    o[6] = fmaf(a[6], di, r1.z);
    o[7] = fmaf(a[7], di, r1.w);
    if (DO_ELU) {
#pragma unroll
        for (int i = 0; i < 8; i++)
            o[i] = (o[i] > 0.f) ? o[i] : expm1f(o[i]);
    }
    float* out = TO_GH ? (float*)g_h : out_param;
    *(float4*)&out[(size_t)node * F + lane * 8] =
        make_float4(o[0], o[1], o[2], o[3]);
    *(float4*)&out[(size_t)node * F + lane * 8 + 4] =
        make_float4(o[4], o[5], o[6], o[7]);
}

// ---------------------------------------------------------------------------
extern "C" void kernel_launch(void* const* d_in, const int* in_sizes, int n_in,
                              void* d_out, int out_size) {
    const float* x   = (const float*)d_in[0];
    const int*   ei  = (const int*)d_in[1];
    const float* Wl0 = (const float*)d_in[2];
    const float* Wr0 = (const float*)d_in[3];
    const float* b0  = (const float*)d_in[4];
    const float* Wl1 = (const float*)d_in[5];
    const float* Wr1 = (const float*)d_in[6];
    const float* b1  = (const float*)d_in[7];
    const float* Wl2 = (const float*)d_in[8];
    const float* Wr2 = (const float*)d_in[9];
    const float* b2  = (const float*)d_in[10];
    float* out = (float*)d_out;

    const int* src = ei;
    const int* dst = ei + NE;

    const int TPB = 256;
    const int gemm_blocks = (NN + 127) / 128;     // 782
    const int gather_blocks64 = (NN + 31) / 32;   // 32 nodes/block (L=8)
    const int gather_blocks32 = (NN + 63) / 64;   // 64 nodes/block (L=4)

    const int SM64 = 4 * 64 * 64 * 4;   // 65536 B dynamic smem (DOUT=64)
    const int SM32 = 4 * 64 * 32 * 4;   // 32768 B (DOUT=32)

    // One-time host-side setup (streams/events + smem limits).
    static cudaStream_t s_side = nullptr;
    static cudaEvent_t  s_fork = nullptr, s_join = nullptr;
    if (s_side == nullptr) {
        cudaStreamCreateWithFlags(&s_side, cudaStreamNonBlocking);
        cudaEventCreateWithFlags(&s_fork, cudaEventDisableTiming);
        cudaEventCreateWithFlags(&s_join, cudaEventDisableTiming);
        cudaFuncSetAttribute(gemm_dual_kernel<64, false>,
                             cudaFuncAttributeMaxDynamicSharedMemorySize, SM64);
        cudaFuncSetAttribute(gemm_dual_kernel<64, true>,
                             cudaFuncAttributeMaxDynamicSharedMemorySize, SM64);
        cudaFuncSetAttribute(gemm_dual_kernel<32, true>,
                             cudaFuncAttributeMaxDynamicSharedMemorySize, SM32);
    }

    // ---- fork: CSR build on side stream, GEMM0 on main stream ----
    cudaEventRecord(s_fork, 0);
    cudaStreamWaitEvent(s_side, s_fork, 0);

    zero_int_kernel<<<(NN + TPB - 1) / TPB, TPB, 0, s_side>>>();
    deg_count_kernel<<<(NE + TPB - 1) / TPB, TPB, 0, s_side>>>(dst);
    scan_a_kernel<<<NBLK, SCAN_BS, 0, s_side>>>();
    scan_b_kernel<<<1, 256, 0, s_side>>>();
    scan_c_kernel<<<(NN + TPB - 1) / TPB, TPB, 0, s_side>>>();
    csr_fill_kernel<<<(NE + TPB - 1) / TPB, TPB, 0, s_side>>>(src, dst);
    cudaEventRecord(s_join, s_side);

    gemm_dual_kernel<64, false><<<gemm_blocks, 256, SM64>>>(x, Wl0, Wr0, b0);

    // ---- join: gather0 needs both CSR and bufA/bufB ----
    cudaStreamWaitEvent(0, s_join, 0);
    gather_kernel<64, true, true><<<gather_blocks64, 256>>>(nullptr);

    // ---- layer 1: 64 -> 64, ELU ----
    gemm_dual_kernel<64, true><<<gemm_blocks, 256, SM64>>>(nullptr, Wl1, Wr1, b1);
    gather_kernel<64, true, true><<<gather_blocks64, 256>>>(nullptr);

    // ---- layer 2: 64 -> 32, no activation, straight to d_out ----
    gemm_dual_kernel<32, true><<<gemm_blocks, 256, SM32>>>(nullptr, Wl2, Wr2, b2);
    gather_kernel<32, false, false><<<gather_blocks32, 256>>>(out);
}

// round 12
// speedup vs baseline: 1.2988x; 1.0496x over previous
#include <cuda_runtime.h>
#include <cuda_fp16.h>
#include <math.h>

#define NN 100000
#define NE 1600000
#define SCAN_BS 512
#define NBLK ((NN + SCAN_BS - 1) / SCAN_BS)   // 196

// -------- device scratch (allocation-free rule: __device__ globals) --------
__device__ float  g_deginv[NN];
__device__ int    g_degi[NN];
__device__ int    g_cursor[NN];
__device__ int    g_rowptr[NN + 1];
__device__ int    g_rowtmp[NN];
__device__ int    g_blocksum[NBLK];
__device__ int    g_blockoff[NBLK];
__device__ int    g_col[NE];                  // CSR: src ids grouped by dst
__device__ __half g_bufAh[NN * 64];           // yl = h @ Wl   (fp16: gather reads this)
__device__ float  g_bufB[NN * 64];            // yr = h @ Wr + b (fp32)
__device__ float  g_h[NN * 64];               // layer activations

// ---------------------------------------------------------------------------
// CSR build (edge structure fixed across layers -> once per call)
// ---------------------------------------------------------------------------
__global__ void zero_int_kernel() {
    int i = blockIdx.x * blockDim.x + threadIdx.x;
    if (i < NN) { g_degi[i] = 0; g_cursor[i] = 0; }
}

__global__ void deg_count_kernel(const int* __restrict__ dst) {
    int e = blockIdx.x * blockDim.x + threadIdx.x;
    if (e < NE) atomicAdd(&g_degi[dst[e]], 1);
}

__global__ void scan_a_kernel() {
    __shared__ int s[SCAN_BS];
    int t = threadIdx.x;
    int i = blockIdx.x * SCAN_BS + t;
    int v = (i < NN) ? g_degi[i] : 0;
    s[t] = v;
    __syncthreads();
#pragma unroll
    for (int off = 1; off < SCAN_BS; off <<= 1) {
        int x = (t >= off) ? s[t - off] : 0;
        __syncthreads();
        s[t] += x;
        __syncthreads();
    }
    if (i < NN) g_rowtmp[i] = s[t] - v;           // exclusive
    if (t == SCAN_BS - 1) g_blocksum[blockIdx.x] = s[t];
}

__global__ void scan_b_kernel() {
    __shared__ int s[256];
    int t = threadIdx.x;
    int v = (t < NBLK) ? g_blocksum[t] : 0;
    s[t] = v;
    __syncthreads();
#pragma unroll
    for (int off = 1; off < 256; off <<= 1) {
        int x = (t >= off) ? s[t - off] : 0;
        __syncthreads();
        s[t] += x;
        __syncthreads();
    }
    if (t < NBLK) g_blockoff[t] = s[t] - v;       // exclusive
}

__global__ void scan_c_kernel() {
    int i = blockIdx.x * blockDim.x + threadIdx.x;
    if (i < NN) {
        g_rowptr[i] = g_rowtmp[i] + g_blockoff[i / SCAN_BS];
        g_deginv[i] = 1.0f / fmaxf((float)g_degi[i], 1.0f);
    }
    if (i == 0) g_rowptr[NN] = NE;
}

__global__ void csr_fill_kernel(const int* __restrict__ src,
                                const int* __restrict__ dst) {
    int e = blockIdx.x * blockDim.x + threadIdx.x;
    if (e >= NE) return;
    int d = dst[e];
    int pos = g_rowptr[d] + atomicAdd(&g_cursor[d], 1);
    g_col[pos] = src[e];
}

// ---------------------------------------------------------------------------
// tf32 helpers
__device__ __forceinline__ unsigned cvt_tf32(float x) {
    unsigned r;
    asm("cvt.rna.tf32.f32 %0, %1;" : "=r"(r) : "f"(x));
    return r;
}
__device__ __forceinline__ void split_tf32(float x, unsigned& hi, unsigned& lo) {
    hi = cvt_tf32(x);
    lo = cvt_tf32(x - __uint_as_float(hi));
}
__device__ __forceinline__ void mma_tf32(float* d,
                                         unsigned a0, unsigned a1,
                                         unsigned a2, unsigned a3,
                                         unsigned b0, unsigned b1) {
    asm("mma.sync.aligned.m16n8k8.row.col.f32.tf32.tf32.f32 "
        "{%0,%1,%2,%3}, {%4,%5,%6,%7}, {%8,%9}, {%0,%1,%2,%3};"
        : "+f"(d[0]), "+f"(d[1]), "+f"(d[2]), "+f"(d[3])
        : "r"(a0), "r"(a1), "r"(a2), "r"(a3), "r"(b0), "r"(b1));
}

// ---------------------------------------------------------------------------
// Dual projection via tensor cores.
// yl (stored fp16 for the gather): 1xTF32 — tf32 precision (~2^-11) matches
// the fp16 storage rounding, so extra MMAs buy nothing for yl.
// yr (fp32, feeds output directly): 3xTF32 (~fp32 accuracy).
// W packed per-fragment in smem: sBlh (Wl hi), sBrh/sBrl (Wr hi/lo).
template<int DOUT, bool FROM_GH>
__global__ void __launch_bounds__(256)
gemm_dual_kernel(const float* __restrict__ hx,
                 const float* __restrict__ Wl,
                 const float* __restrict__ Wr,
                 const float* __restrict__ bias) {
    constexpr int JT    = DOUT / 8;              // j-tiles (8 or 4)
    constexpr int FRAGS = 8 * JT;                // (kb, jt) fragments
    constexpr int FSZ   = FRAGS * 64;            // floats per packed array

    extern __shared__ float smem[];
    float* sBlh = smem;
    float* sBrh = sBlh + FSZ;
    float* sBrl = sBrh + FSZ;

    const float* __restrict__ h = FROM_GH ? (const float*)g_h : hx;

    const int t    = threadIdx.x;
    const int wid  = t >> 5;
    const int lane = t & 31;
    const int gid  = lane >> 2;                  // groupID 0..7
    const int tig  = lane & 3;                   // thread-in-group 0..3

    // ---- stage: split W into packed tf32 fragments ----
    for (int idx = t; idx < FSZ; idx += 256) {
        const int frag = idx >> 6;
        const int li   = idx & 63;
        const int ln   = li >> 1;
        const int i    = li & 1;
        const int kb   = frag / JT;
        const int jt   = frag % JT;
        const int k    = kb * 8 + (ln & 3) + 4 * i;
        const int j    = jt * 8 + (ln >> 2);
        sBlh[idx] = __uint_as_float(cvt_tf32(Wl[k * DOUT + j]));
        unsigned hi, lo;
        split_tf32(Wr[k * DOUT + j], hi, lo);
        sBrh[idx] = __uint_as_float(hi);
        sBrl[idx] = __uint_as_float(lo);
    }
    __syncthreads();

    const int node0 = blockIdx.x * 128 + wid * 16;
    const int r0 = node0 + gid;                  // rows r0, r0+8
    const bool ok0 = (r0 < NN);
    const bool ok1 = (r0 + 8 < NN);

    float dL[JT][4], dR[JT][4];
#pragma unroll
    for (int jt = 0; jt < JT; jt++) {
        float bc0 = bias[jt * 8 + 2 * tig];
        float bc1 = bias[jt * 8 + 2 * tig + 1];
        dL[jt][0] = dL[jt][1] = dL[jt][2] = dL[jt][3] = 0.f;
        dR[jt][0] = bc0; dR[jt][1] = bc1;
        dR[jt][2] = bc0; dR[jt][3] = bc1;
    }

#pragma unroll
    for (int kb = 0; kb < 8; kb++) {
        const int k0 = kb * 8;
        float fa0 = ok0 ? h[(size_t)r0 * 64 + k0 + tig] : 0.f;
        float fa1 = ok1 ? h[(size_t)(r0 + 8) * 64 + k0 + tig] : 0.f;
        float fa2 = ok0 ? h[(size_t)r0 * 64 + k0 + tig + 4] : 0.f;
        float fa3 = ok1 ? h[(size_t)(r0 + 8) * 64 + k0 + tig + 4] : 0.f;
        unsigned ah0, al0, ah1, al1, ah2, al2, ah3, al3;
        split_tf32(fa0, ah0, al0);
        split_tf32(fa1, ah1, al1);
        split_tf32(fa2, ah2, al2);
        split_tf32(fa3, ah3, al3);

#pragma unroll
        for (int jt = 0; jt < JT; jt++) {
            const int fbase = (kb * JT + jt) * 64 + lane * 2;
            const float2 blh = *(const float2*)&sBlh[fbase];
            const float2 brh = *(const float2*)&sBrh[fbase];
            const float2 brl = *(const float2*)&sBrl[fbase];

            // yl: single tf32 pass (matches fp16 storage precision)
            mma_tf32(dL[jt], ah0, ah1, ah2, ah3,
                     __float_as_uint(blh.x), __float_as_uint(blh.y));

            // yr: 3xTF32 (lo*hi + hi*lo + hi*hi)
            mma_tf32(dR[jt], al0, al1, al2, al3,
                     __float_as_uint(brh.x), __float_as_uint(brh.y));
            mma_tf32(dR[jt], ah0, ah1, ah2, ah3,
                     __float_as_uint(brl.x), __float_as_uint(brl.y));
            mma_tf32(dR[jt], ah0, ah1, ah2, ah3,
                     __float_as_uint(brh.x), __float_as_uint(brh.y));
        }
    }

    // epilogue: yl -> fp16 (half2 stores), yr -> fp32
#pragma unroll
    for (int jt = 0; jt < JT; jt++) {
        const int j0 = jt * 8 + 2 * tig;
        if (ok0) {
            *(__half2*)&g_bufAh[(size_t)r0 * DOUT + j0] =
                __floats2half2_rn(dL[jt][0], dL[jt][1]);
            *(float2*)&g_bufB[(size_t)r0 * DOUT + j0] = make_float2(dR[jt][0], dR[jt][1]);
        }
        if (ok1) {
            *(__half2*)&g_bufAh[(size_t)(r0 + 8) * DOUT + j0] =
                __floats2half2_rn(dL[jt][2], dL[jt][3]);
            *(float2*)&g_bufB[(size_t)(r0 + 8) * DOUT + j0] = make_float2(dR[jt][2], dR[jt][3]);
        }
    }
}

// ---------------------------------------------------------------------------
// Fused gather + epilogue: out[n] = [ELU]( mean_e yl_h16[col[e]] + yr[n] )
// yl is fp16: one uint4 (8 halves = 16B) per lane per edge. fp32 accumulation.
template<int F, bool DO_ELU, bool TO_GH>
__global__ void __launch_bounds__(256)
gather_kernel(float* __restrict__ out_param) {
    constexpr int L = F / 8;               // lanes/node: 8 (F=64) or 4 (F=32)
    const int t    = threadIdx.x;
    const int grp  = t / L;
    const int lane = t % L;
    const int node = blockIdx.x * (256 / L) + grp;
    if (node >= NN) return;

    const int beg = g_rowptr[node];
    const int end = g_rowptr[node + 1];
    const __half* __restrict__ A = g_bufAh;

    float a[8] = {0.f, 0.f, 0.f, 0.f, 0.f, 0.f, 0.f, 0.f};
    for (int e = beg; e < end; e++) {
        const int s = g_col[e];
        const uint4 v = *(const uint4*)&A[(size_t)s * F + lane * 8];
        const __half2* hp = (const __half2*)&v;
        float2 f0 = __half22float2(hp[0]);
        float2 f1 = __half22float2(hp[1]);
        float2 f2 = __half22float2(hp[2]);
        float2 f3 = __half22float2(hp[3]);
        a[0] += f0.x; a[1] += f0.y;
        a[2] += f1.x; a[3] += f1.y;
        a[4] += f2.x; a[5] += f2.y;
        a[6] += f3.x; a[7] += f3.y;
    }

    const float di = g_deginv[node];
    const float4 r0 = *(const float4*)&g_bufB[(size_t)node * F + lane * 8];
    const float4 r1 = *(const float4*)&g_bufB[(size_t)node * F + lane * 8 + 4];
    float o[8];
    o[0] = fmaf(a[0], di, r0.x);
    o[1] = fmaf(a[1], di, r0.y);
    o[2] = fmaf(a[2], di, r0.z);
    o[3] = fmaf(a[3], di, r0.w);
    o[4] = fmaf(a[4], di, r1.x);
    o[5] = fmaf(a[5], di, r1.y);
    o[6] = fmaf(a[6], di, r1.z);
    o[7] = fmaf(a[7], di, r1.w);
    if (DO_ELU) {
#pragma unroll
        for (int i = 0; i < 8; i++)
            o[i] = (o[i] > 0.f) ? o[i] : expm1f(o[i]);
    }
    float* out = TO_GH ? (float*)g_h : out_param;
    *(float4*)&out[(size_t)node * F + lane * 8] =
        make_float4(o[0], o[1], o[2], o[3]);
    *(float4*)&out[(size_t)node * F + lane * 8 + 4] =
        make_float4(o[4], o[5], o[6], o[7]);
}

// ---------------------------------------------------------------------------
extern "C" void kernel_launch(void* const* d_in, const int* in_sizes, int n_in,
                              void* d_out, int out_size) {
    const float* x   = (const float*)d_in[0];
    const int*   ei  = (const int*)d_in[1];
    const float* Wl0 = (const float*)d_in[2];
    const float* Wr0 = (const float*)d_in[3];
    const float* b0  = (const float*)d_in[4];
    const float* Wl1 = (const float*)d_in[5];
    const float* Wr1 = (const float*)d_in[6];
    const float* b1  = (const float*)d_in[7];
    const float* Wl2 = (const float*)d_in[8];
    const float* Wr2 = (const float*)d_in[9];
    const float* b2  = (const float*)d_in[10];
    float* out = (float*)d_out;

    const int* src = ei;
    const int* dst = ei + NE;

    const int TPB = 256;
    const int gemm_blocks = (NN + 127) / 128;     // 782
    const int gather_blocks64 = (NN + 31) / 32;   // 32 nodes/block (L=8)
    const int gather_blocks32 = (NN + 63) / 64;   // 64 nodes/block (L=4)

    const int SM64 = 3 * 64 * 64 * 4;   // 49152 B dynamic smem (DOUT=64)
    const int SM32 = 3 * 64 * 32 * 4;   // 24576 B (DOUT=32)

    // One-time host-side setup (streams/events + smem limits).
    static cudaStream_t s_side = nullptr;
    static cudaEvent_t  s_fork = nullptr, s_join = nullptr;
    if (s_side == nullptr) {
        cudaStreamCreateWithFlags(&s_side, cudaStreamNonBlocking);
        cudaEventCreateWithFlags(&s_fork, cudaEventDisableTiming);
        cudaEventCreateWithFlags(&s_join, cudaEventDisableTiming);
        cudaFuncSetAttribute(gemm_dual_kernel<64, false>,
                             cudaFuncAttributeMaxDynamicSharedMemorySize, SM64);
        cudaFuncSetAttribute(gemm_dual_kernel<64, true>,
                             cudaFuncAttributeMaxDynamicSharedMemorySize, SM64);
        cudaFuncSetAttribute(gemm_dual_kernel<32, true>,
                             cudaFuncAttributeMaxDynamicSharedMemorySize, SM32);
    }

    // ---- fork: CSR build on side stream, GEMM0 on main stream ----
    cudaEventRecord(s_fork, 0);
    cudaStreamWaitEvent(s_side, s_fork, 0);

    zero_int_kernel<<<(NN + TPB - 1) / TPB, TPB, 0, s_side>>>();
    deg_count_kernel<<<(NE + TPB - 1) / TPB, TPB, 0, s_side>>>(dst);
    scan_a_kernel<<<NBLK, SCAN_BS, 0, s_side>>>();
    scan_b_kernel<<<1, 256, 0, s_side>>>();
    scan_c_kernel<<<(NN + TPB - 1) / TPB, TPB, 0, s_side>>>();
    csr_fill_kernel<<<(NE + TPB - 1) / TPB, TPB, 0, s_side>>>(src, dst);
    cudaEventRecord(s_join, s_side);

    gemm_dual_kernel<64, false><<<gemm_blocks, 256, SM64>>>(x, Wl0, Wr0, b0);

    // ---- join: gather0 needs both CSR and bufA/bufB ----
    cudaStreamWaitEvent(0, s_join, 0);
    gather_kernel<64, true, true><<<gather_blocks64, 256>>>(nullptr);

    // ---- layer 1: 64 -> 64, ELU ----
    gemm_dual_kernel<64, true><<<gemm_blocks, 256, SM64>>>(nullptr, Wl1, Wr1, b1);
    gather_kernel<64, true, true><<<gather_blocks64, 256>>>(nullptr);

    // ---- layer 2: 64 -> 32, no activation, straight to d_out ----
    gemm_dual_kernel<32, true><<<gemm_blocks, 256, SM32>>>(nullptr, Wl2, Wr2, b2);
    gather_kernel<32, false, false><<<gather_blocks32, 256>>>(out);
}

// round 13
// speedup vs baseline: 1.5440x; 1.1888x over previous
#include <cuda_runtime.h>
#include <cuda_fp16.h>
#include <math.h>

#define NN 100000
#define NE 1600000
#define SCAN_BS 512
#define NBLK ((NN + SCAN_BS - 1) / SCAN_BS)   // 196

// -------- device scratch (allocation-free rule: __device__ globals) --------
__device__ float  g_deginv[NN];
__device__ int    g_degi[NN];
__device__ int    g_cursor[NN];
__device__ int    g_rowptr[NN + 1];
__device__ int    g_rowtmp[NN];
__device__ int    g_blocksum[NBLK];
__device__ int    g_blockoff[NBLK];
__device__ int    g_col[NE];                  // CSR: src ids grouped by dst
__device__ __half g_bufAh[NN * 64];           // yl (fp16: gather reads this)
__device__ float  g_bufB[NN * 64];            // yr (fp32)
__device__ __half g_h16[NN * 64];             // activations, fp16 (GEMM A-feed)

// ---------------------------------------------------------------------------
// CSR build (edge structure fixed across layers -> once per call)
// ---------------------------------------------------------------------------
__global__ void zero_int_kernel() {
    int i = blockIdx.x * blockDim.x + threadIdx.x;
    if (i < NN) { g_degi[i] = 0; g_cursor[i] = 0; }
}

__global__ void deg_count_kernel(const int* __restrict__ dst) {
    int e = blockIdx.x * blockDim.x + threadIdx.x;
    if (e < NE) atomicAdd(&g_degi[dst[e]], 1);
}

__global__ void scan_a_kernel() {
    __shared__ int s[SCAN_BS];
    int t = threadIdx.x;
    int i = blockIdx.x * SCAN_BS + t;
    int v = (i < NN) ? g_degi[i] : 0;
    s[t] = v;
    __syncthreads();
#pragma unroll
    for (int off = 1; off < SCAN_BS; off <<= 1) {
        int x = (t >= off) ? s[t - off] : 0;
        __syncthreads();
        s[t] += x;
        __syncthreads();
    }
    if (i < NN) g_rowtmp[i] = s[t] - v;           // exclusive
    if (t == SCAN_BS - 1) g_blocksum[blockIdx.x] = s[t];
}

__global__ void scan_b_kernel() {
    __shared__ int s[256];
    int t = threadIdx.x;
    int v = (t < NBLK) ? g_blocksum[t] : 0;
    s[t] = v;
    __syncthreads();
#pragma unroll
    for (int off = 1; off < 256; off <<= 1) {
        int x = (t >= off) ? s[t - off] : 0;
        __syncthreads();
        s[t] += x;
        __syncthreads();
    }
    if (t < NBLK) g_blockoff[t] = s[t] - v;       // exclusive
}

__global__ void scan_c_kernel() {
    int i = blockIdx.x * blockDim.x + threadIdx.x;
    if (i < NN) {
        g_rowptr[i] = g_rowtmp[i] + g_blockoff[i / SCAN_BS];
        g_deginv[i] = 1.0f / fmaxf((float)g_degi[i], 1.0f);
    }
    if (i == 0) g_rowptr[NN] = NE;
}

__global__ void csr_fill_kernel(const int* __restrict__ src,
                                const int* __restrict__ dst) {
    int e = blockIdx.x * blockDim.x + threadIdx.x;
    if (e >= NE) return;
    int d = dst[e];
    int pos = g_rowptr[d] + atomicAdd(&g_cursor[d], 1);
    g_col[pos] = src[e];
}

// ---------------------------------------------------------------------------
// fp16 pack helpers + f16 MMA
__device__ __forceinline__ unsigned pack_h2(float a, float b) {
    __half2 h = __floats2half2_rn(a, b);
    return *reinterpret_cast<unsigned*>(&h);
}
__device__ __forceinline__ unsigned pack_2h(__half a, __half b) {
    __half2 h = __halves2half2(a, b);
    return *reinterpret_cast<unsigned*>(&h);
}
__device__ __forceinline__ void mma_f16(float* d,
                                        unsigned a0, unsigned a1,
                                        unsigned a2, unsigned a3,
                                        unsigned b0, unsigned b1) {
    asm("mma.sync.aligned.m16n8k16.row.col.f32.f16.f16.f32 "
        "{%0,%1,%2,%3}, {%4,%5,%6,%7}, {%8,%9}, {%0,%1,%2,%3};"
        : "+f"(d[0]), "+f"(d[1]), "+f"(d[2]), "+f"(d[3])
        : "r"(a0), "r"(a1), "r"(a2), "r"(a3), "r"(b0), "r"(b1));
}

// ---------------------------------------------------------------------------
// Convert fp32 input x -> fp16 activations (layer-0 A-feed).
__global__ void cvt_x_kernel(const float* __restrict__ x) {
    int i = blockIdx.x * blockDim.x + threadIdx.x;   // one per 8 elements
    if (i >= NN * 8) return;
    const float4 v0 = *(const float4*)&x[(size_t)i * 8];
    const float4 v1 = *(const float4*)&x[(size_t)i * 8 + 4];
    uint4 u;
    u.x = pack_h2(v0.x, v0.y);
    u.y = pack_h2(v0.z, v0.w);
    u.z = pack_h2(v1.x, v1.y);
    u.w = pack_h2(v1.z, v1.w);
    *(uint4*)&g_h16[(size_t)i * 8] = u;
}

// ---------------------------------------------------------------------------
// Dual projection via fp16 tensor cores, A = g_h16 (fp16 activations).
// yl: 1 fp16 MMA (precision matches fp16 storage).
// yr: 2 fp16 MMAs with exact hi/lo fp16 split of Wr (fp16 products are exact
//     in fp32 accumulation, so yr error ~ h's own fp16 rounding only).
// Per (kb,jt): 3 LDS.64 + 3 MMA.  4 k-blocks of 16.
template<int DOUT>
__global__ void __launch_bounds__(256)
gemm_dual_kernel(const float* __restrict__ Wl,
                 const float* __restrict__ Wr,
                 const float* __restrict__ bias) {
    constexpr int JT    = DOUT / 8;              // j-tiles (8 or 4)
    constexpr int FRAGS = 4 * JT;                // (kb, jt) fragments, kb of 16
    constexpr int FSZ   = FRAGS * 64;            // b32 elements per packed array

    __shared__ unsigned sBl[FSZ];                // Wl fp16 pairs
    __shared__ unsigned sBrh[FSZ];               // Wr hi fp16 pairs
    __shared__ unsigned sBrl[FSZ];               // Wr lo fp16 pairs

    const int t    = threadIdx.x;
    const int wid  = t >> 5;
    const int lane = t & 31;
    const int gid  = lane >> 2;                  // groupID 0..7
    const int tig  = lane & 3;                   // thread-in-group 0..3

    // ---- stage: pack W into per-fragment fp16 layout ----
    // b-reg i of fragment (kb,jt), lane ln holds W[k..k+1][j]:
    //   k = kb*16 + 2*(ln&3) + 8*i,  j = jt*8 + (ln>>2)
    for (int idx = t; idx < FSZ; idx += 256) {
        const int frag = idx >> 6;
        const int li   = idx & 63;
        const int ln   = li >> 1;
        const int i    = li & 1;
        const int kb   = frag / JT;
        const int jt   = frag % JT;
        const int k    = kb * 16 + 2 * (ln & 3) + 8 * i;
        const int j    = jt * 8 + (ln >> 2);
        const float wl0 = Wl[k * DOUT + j];
        const float wl1 = Wl[(k + 1) * DOUT + j];
        sBl[idx] = pack_h2(wl0, wl1);
        const float wr0 = Wr[k * DOUT + j];
        const float wr1 = Wr[(k + 1) * DOUT + j];
        const __half h0 = __float2half_rn(wr0);
        const __half h1 = __float2half_rn(wr1);
        sBrh[idx] = pack_2h(h0, h1);
        sBrl[idx] = pack_h2(wr0 - __half2float(h0), wr1 - __half2float(h1));
    }
    __syncthreads();

    const int node0 = blockIdx.x * 128 + wid * 16;
    const int r0 = node0 + gid;                  // rows r0, r0+8
    const bool ok0 = (r0 < NN);
    const bool ok1 = (r0 + 8 < NN);

    float dL[JT][4], dR[JT][4];
#pragma unroll
    for (int jt = 0; jt < JT; jt++) {
        float bc0 = bias[jt * 8 + 2 * tig];
        float bc1 = bias[jt * 8 + 2 * tig + 1];
        dL[jt][0] = dL[jt][1] = dL[jt][2] = dL[jt][3] = 0.f;
        dR[jt][0] = bc0; dR[jt][1] = bc1;
        dR[jt][2] = bc0; dR[jt][3] = bc1;
    }

#pragma unroll
    for (int kb = 0; kb < 4; kb++) {
        const int k0 = kb * 16;
        // A fragment (m16n8k16): a0/a2 row r0, a1/a3 row r0+8; 2 halves each
        const unsigned a0 = ok0 ? *(const unsigned*)&g_h16[(size_t)r0 * 64 + k0 + 2 * tig] : 0u;
        const unsigned a1 = ok1 ? *(const unsigned*)&g_h16[(size_t)(r0 + 8) * 64 + k0 + 2 * tig] : 0u;
        const unsigned a2 = ok0 ? *(const unsigned*)&g_h16[(size_t)r0 * 64 + k0 + 2 * tig + 8] : 0u;
        const unsigned a3 = ok1 ? *(const unsigned*)&g_h16[(size_t)(r0 + 8) * 64 + k0 + 2 * tig + 8] : 0u;

#pragma unroll
        for (int jt = 0; jt < JT; jt++) {
            const int fbase = (kb * JT + jt) * 64 + lane * 2;
            const uint2 bl = *(const uint2*)&sBl[fbase];
            const uint2 bh = *(const uint2*)&sBrh[fbase];
            const uint2 bo = *(const uint2*)&sBrl[fbase];
            mma_f16(dL[jt], a0, a1, a2, a3, bl.x, bl.y);
            mma_f16(dR[jt], a0, a1, a2, a3, bh.x, bh.y);
            mma_f16(dR[jt], a0, a1, a2, a3, bo.x, bo.y);
        }
    }

    // epilogue: yl -> fp16, yr -> fp32
#pragma unroll
    for (int jt = 0; jt < JT; jt++) {
        const int j0 = jt * 8 + 2 * tig;
        if (ok0) {
            *(__half2*)&g_bufAh[(size_t)r0 * DOUT + j0] =
                __floats2half2_rn(dL[jt][0], dL[jt][1]);
            *(float2*)&g_bufB[(size_t)r0 * DOUT + j0] = make_float2(dR[jt][0], dR[jt][1]);
        }
        if (ok1) {
            *(__half2*)&g_bufAh[(size_t)(r0 + 8) * DOUT + j0] =
                __floats2half2_rn(dL[jt][2], dL[jt][3]);
            *(float2*)&g_bufB[(size_t)(r0 + 8) * DOUT + j0] = make_float2(dR[jt][2], dR[jt][3]);
        }
    }
}

// ---------------------------------------------------------------------------
// Fused gather + epilogue: out[n] = [ELU]( mean_e yl_h16[col[e]] + yr[n] )
// yl fp16: one uint4 (8 halves) per lane per edge; fp32 accumulation.
// TO_GH: write activations as fp16 (g_h16); else fp32 to out_param.
template<int F, bool DO_ELU, bool TO_GH>
__global__ void __launch_bounds__(256)
gather_kernel(float* __restrict__ out_param) {
    constexpr int L = F / 8;               // lanes/node: 8 (F=64) or 4 (F=32)
    const int t    = threadIdx.x;
    const int grp  = t / L;
    const int lane = t % L;
    const int node = blockIdx.x * (256 / L) + grp;
    if (node >= NN) return;

    const int beg = g_rowptr[node];
    const int end = g_rowptr[node + 1];
    const __half* __restrict__ A = g_bufAh;

    float a[8] = {0.f, 0.f, 0.f, 0.f, 0.f, 0.f, 0.f, 0.f};
    for (int e = beg; e < end; e++) {
        const int s = g_col[e];
        const uint4 v = *(const uint4*)&A[(size_t)s * F + lane * 8];
        const __half2* hp = (const __half2*)&v;
        float2 f0 = __half22float2(hp[0]);
        float2 f1 = __half22float2(hp[1]);
        float2 f2 = __half22float2(hp[2]);
        float2 f3 = __half22float2(hp[3]);
        a[0] += f0.x; a[1] += f0.y;
        a[2] += f1.x; a[3] += f1.y;
        a[4] += f2.x; a[5] += f2.y;
        a[6] += f3.x; a[7] += f3.y;
    }

    const float di = g_deginv[node];
    const float4 r0 = *(const float4*)&g_bufB[(size_t)node * F + lane * 8];
    const float4 r1 = *(const float4*)&g_bufB[(size_t)node * F + lane * 8 + 4];
    float o[8];
    o[0] = fmaf(a[0], di, r0.x);
    o[1] = fmaf(a[1], di, r0.y);
    o[2] = fmaf(a[2], di, r0.z);
    o[3] = fmaf(a[3], di, r0.w);
    o[4] = fmaf(a[4], di, r1.x);
    o[5] = fmaf(a[5], di, r1.y);
    o[6] = fmaf(a[6], di, r1.z);
    o[7] = fmaf(a[7], di, r1.w);
    if (DO_ELU) {
#pragma unroll
        for (int i = 0; i < 8; i++)
            o[i] = (o[i] > 0.f) ? o[i] : expm1f(o[i]);
    }
    if (TO_GH) {
        uint4 u;
        u.x = pack_h2(o[0], o[1]);
        u.y = pack_h2(o[2], o[3]);
        u.z = pack_h2(o[4], o[5]);
        u.w = pack_h2(o[6], o[7]);
        *(uint4*)&g_h16[(size_t)node * F + lane * 8] = u;
    } else {
        *(float4*)&out_param[(size_t)node * F + lane * 8] =
            make_float4(o[0], o[1], o[2], o[3]);
        *(float4*)&out_param[(size_t)node * F + lane * 8 + 4] =
            make_float4(o[4], o[5], o[6], o[7]);
    }
}

// ---------------------------------------------------------------------------
extern "C" void kernel_launch(void* const* d_in, const int* in_sizes, int n_in,
                              void* d_out, int out_size) {
    const float* x   = (const float*)d_in[0];
    const int*   ei  = (const int*)d_in[1];
    const float* Wl0 = (const float*)d_in[2];
    const float* Wr0 = (const float*)d_in[3];
    const float* b0  = (const float*)d_in[4];
    const float* Wl1 = (const float*)d_in[5];
    const float* Wr1 = (const float*)d_in[6];
    const float* b1  = (const float*)d_in[7];
    const float* Wl2 = (const float*)d_in[8];
    const float* Wr2 = (const float*)d_in[9];
    const float* b2  = (const float*)d_in[10];
    float* out = (float*)d_out;

    const int* src = ei;
    const int* dst = ei + NE;

    const int TPB = 256;
    const int gemm_blocks = (NN + 127) / 128;     // 782
    const int gather_blocks64 = (NN + 31) / 32;   // 32 nodes/block (L=8)
    const int gather_blocks32 = (NN + 63) / 64;   // 64 nodes/block (L=4)

    // One-time host-side setup (stream + events only).
    static cudaStream_t s_side = nullptr;
    static cudaEvent_t  s_fork = nullptr, s_join = nullptr;
    if (s_side == nullptr) {
        cudaStreamCreateWithFlags(&s_side, cudaStreamNonBlocking);
        cudaEventCreateWithFlags(&s_fork, cudaEventDisableTiming);
        cudaEventCreateWithFlags(&s_join, cudaEventDisableTiming);
    }

    // ---- fork: CSR build on side stream, cvt+GEMM0 on main stream ----
    cudaEventRecord(s_fork, 0);
    cudaStreamWaitEvent(s_side, s_fork, 0);

    zero_int_kernel<<<(NN + TPB - 1) / TPB, TPB, 0, s_side>>>();
    deg_count_kernel<<<(NE + TPB - 1) / TPB, TPB, 0, s_side>>>(dst);
    scan_a_kernel<<<NBLK, SCAN_BS, 0, s_side>>>();
    scan_b_kernel<<<1, 256, 0, s_side>>>();
    scan_c_kernel<<<(NN + TPB - 1) / TPB, TPB, 0, s_side>>>();
    csr_fill_kernel<<<(NE + TPB - 1) / TPB, TPB, 0, s_side>>>(src, dst);
    cudaEventRecord(s_join, s_side);

    cvt_x_kernel<<<(NN * 8 + TPB - 1) / TPB, TPB>>>(x);
    gemm_dual_kernel<64><<<gemm_blocks, 256>>>(Wl0, Wr0, b0);

    // ---- join: gather0 needs both CSR and bufAh/bufB ----
    cudaStreamWaitEvent(0, s_join, 0);
    gather_kernel<64, true, true><<<gather_blocks64, 256>>>(nullptr);

    // ---- layer 1: 64 -> 64, ELU ----
    gemm_dual_kernel<64><<<gemm_blocks, 256>>>(Wl1, Wr1, b1);
    gather_kernel<64, true, true><<<gather_blocks64, 256>>>(nullptr);

    // ---- layer 2: 64 -> 32, no activation, straight to d_out ----
    gemm_dual_kernel<32><<<gemm_blocks, 256>>>(Wl2, Wr2, b2);
    gather_kernel<32, false, false><<<gather_blocks32, 256>>>(out);
}